// round 11
// baseline (speedup 1.0000x reference)
#include <cuda_runtime.h>
#include <cstdint>
#include <cstddef>

#define NEGV (-1e30f)

static const int Bn = 128;
static const int Tn = 2048;
static const int Nn = 64;
static const int Ln = 256;

// ---------------------------------------------------------------------------
// Packed f32x2 helpers (Blackwell: fma.rn.f32x2 only reachable via PTX)
// ---------------------------------------------------------------------------
__device__ __forceinline__ void fma2(unsigned long long& acc,
                                     unsigned long long e,
                                     unsigned long long w) {
    asm("fma.rn.f32x2 %0, %1, %2, %0;" : "+l"(acc) : "l"(e), "l"(w));
}
__device__ __forceinline__ unsigned long long add2(unsigned long long a,
                                                   unsigned long long b) {
    unsigned long long r;
    asm("add.rn.f32x2 %0, %1, %2;" : "=l"(r) : "l"(a), "l"(b));
    return r;
}
__device__ __forceinline__ void cp4(void* dst, const void* src) {
    unsigned int d = (unsigned int)__cvta_generic_to_shared(dst);
    asm volatile("cp.async.ca.shared.global [%0], [%1], 4;" :: "r"(d), "l"(src) : "memory");
}
#define CP_COMMIT() asm volatile("cp.async.commit_group;" ::: "memory")
#define CP_WAIT5()  asm volatile("cp.async.wait_group 5;" ::: "memory")
// private per-role barriers (id, thread count)
#define NBAR(id, cnt) asm volatile("bar.sync %0, %1;" :: "r"(id), "r"(cnt) : "memory")

// ---------------------------------------------------------------------------
// ONE CTA per batch (grid 128 <= 148 SMs -> 1 CTA/SM, single wave).
// 192 threads, two independent roles with PRIVATE named barriers:
//   tid   0..63  (warps 0-1): fcc — R5 design: thread = class n, cp.async smem
//       ring for x_t, smem E exchange; exact power-of-2 renorm (integer
//       exponent strip of E_prev[0]); exp(x_t) precomputed one step early.
//       Per-step sync: bar.sync 1, 64.
//   tid  64..191 (warps 2-5): fac — thread = 2 target lanes; emissions
//       x[t][tg] prefetched into per-thread register queues (fixed addresses,
//       L1-resident); only shared state is the 4-float warp boundary.
//       Per-step sync: bar.sync 2, 128.
// Combine is in-CTA: one final __syncthreads (all 192), thread 0 subtracts.
// ---------------------------------------------------------------------------
__global__ void __launch_bounds__(192, 1) asg_main(
    const float* __restrict__ xin_all, const int* __restrict__ tgt_all,
    const int* __restrict__ tsz_all, const float* __restrict__ trans,
    float* __restrict__ out)
{
    __shared__ __align__(16) float sx[8][64];     // fcc x_t staging ring
    __shared__ __align__(16) float sE[2][64];     // fcc state, double buffered
    __shared__ float sfb[2][4];                   // fac warp-boundary, dbl buf
    __shared__ float s_res[2];                    // [0]=fcc, [1]=fac

    const int b = blockIdx.x;
    const int tid = threadIdx.x;
    const float* xin = xin_all + (size_t)b * Tn * Nn;

    if (tid < 64) {
        // ================= fcc: scaled-exp forward scan ====================
        const int n = tid;

        unsigned long long w2[32];                // exp(trans[n, :]) packed
        const float* wr = trans + n * Nn;
#pragma unroll
        for (int j = 0; j < 32; j++) {
            float wa = __expf(wr[2 * j]);
            float wb = __expf(wr[2 * j + 1]);
            asm("mov.b64 %0, {%1, %2};" : "=l"(w2[j]) : "f"(wa), "f"(wb));
        }
        sE[0][n] = __expf(xin[n]);                // alpha0 = x0
        int iexp = 0;                             // sum of stripped exponents

        // prologue: stage x_t for t = 1..6
#pragma unroll
        for (int tt = 1; tt <= 6; tt++) {
            cp4(&sx[tt & 7][n], xin + (size_t)tt * Nn + n);
            CP_COMMIT();
        }
        CP_WAIT5();
        NBAR(1, 64);

        float p_cur = __expf(sx[1][n]);           // exp(x[1]) (slot 1 staged)

        for (int t = 1; t < Tn; ++t) {
            const int rb = (t + 1) & 1;           // E read buffer
            const int wbuf = t & 1;               // E write buffer

            float e0 = sE[rb][0];                 // scalar broadcast LDS
            const ulonglong2* ep = reinterpret_cast<const ulonglong2*>(sE[rb]);
            unsigned long long acc0 = 0ull, acc1 = 0ull, acc2 = 0ull, acc3 = 0ull;
#pragma unroll
            for (int k2 = 0; k2 < 16; k2++) {
                ulonglong2 e = ep[k2];            // broadcast LDS.128
                if (k2 & 1) {
                    fma2(acc2, e.x, w2[2 * k2]);
                    fma2(acc3, e.y, w2[2 * k2 + 1]);
                } else {
                    fma2(acc0, e.x, w2[2 * k2]);
                    fma2(acc1, e.y, w2[2 * k2 + 1]);
                }
            }
            unsigned long long s = add2(add2(acc0, acc1), add2(acc2, acc3));
            float slo, shi;
            asm("mov.b64 {%0, %1}, %2;" : "=f"(slo), "=f"(shi) : "l"(s));
            float S = slo + shi;

            // exact renorm: strip E_prev[0]'s exponent (uniform across threads)
            int k = ((__float_as_int(e0) >> 23) & 0xff) - 127;
            iexp += k;
            float En = S * p_cur;                 // p_cur precomputed last iter
            En = __int_as_float(__float_as_int(En) - (k << 23));  // * 2^-k
            sE[wbuf][n] = En;

            // off-chain: pre-exp next step's x (slot t+1 staged >= 5 ago),
            // then ring maintenance for t+6.
            if (t + 1 < Tn) p_cur = __expf(sx[(t + 1) & 7][n]);
            int tpf = t + 6; if (tpf > Tn - 1) tpf = Tn - 1;
            cp4(&sx[(t + 6) & 7][n], xin + (size_t)tpf * Nn + n);
            CP_COMMIT();
            CP_WAIT5();
            NBAR(1, 64);
        }

        // epilogue: fcc = iexp*ln2 + ln(sum_n E[n]); last buffer = 2047&1 = 1
        if (tid < 32) {
            float v = sE[1][tid] + sE[1][tid + 32];
#pragma unroll
            for (int o = 16; o > 0; o >>= 1)
                v += __shfl_xor_sync(0xffffffffu, v, o);
            if (tid == 0)
                s_res[0] = (float)iexp * 0.69314718055994531f + __logf(v);
        }
    } else {
        // ================= fac: log-domain constrained scan ================
        const int f = tid - 64;                   // 0..127, lanes 2f, 2f+1
        const int l0 = 2 * f, l1 = 2 * f + 1;
        const int tg0 = tgt_all[b * Ln + l0];
        const int tg1 = tgt_all[b * Ln + l1];
        const int tgm = (l0 > 0) ? tgt_all[b * Ln + l0 - 1] : 0;
        const float ts0 = trans[tg0 * Nn + tg0];
        const float ts1 = trans[tg1 * Nn + tg1];
        const float tm0 = trans[tg0 * Nn + tgm];  // move into l0 (unused if l0==0)
        const float tm1 = trans[tg1 * Nn + tg0];  // move into l1
        const int tssel = tsz_all[b];

        float a0 = (l0 == 0) ? xin[tg0] : NEGV;   // alpha0[0] = x0[target[0]]
        float a1 = NEGV;
        if ((f & 31) == 31) sfb[0][f >> 5] = a1;

        // emission register queues (fixed per-thread addresses): t, t+1, t+2
        float e0q0 = __ldg(xin + 1 * (size_t)Nn + tg0);
        float e1q0 = __ldg(xin + 1 * (size_t)Nn + tg1);
        float e0q1 = __ldg(xin + 2 * (size_t)Nn + tg0);
        float e1q1 = __ldg(xin + 2 * (size_t)Nn + tg1);
        float e0q2 = __ldg(xin + 3 * (size_t)Nn + tg0);
        float e1q2 = __ldg(xin + 3 * (size_t)Nn + tg1);
        NBAR(2, 128);

        for (int t = 1; t < Tn; ++t) {
            const int rb = (t + 1) & 1;
            const int wbuf = t & 1;

            float ap = __shfl_up_sync(0xffffffffu, a1, 1);
            float e0 = e0q0, e1 = e1q0;
            if ((f & 31) == 0) ap = (f == 0) ? NEGV : sfb[rb][(f >> 5) - 1];

            float st1 = a1 + ts1, mv1 = a0 + tm1; // uses OLD a0
            float h1 = fmaxf(st1, mv1), lo1 = fminf(st1, mv1);
            float na1 = e1 + h1 + __logf(1.0f + __expf(lo1 - h1));

            float st0 = a0 + ts0, mv0 = ap + tm0;
            float h0 = fmaxf(st0, mv0), lo0 = fminf(st0, mv0);
            float na0 = e0 + h0 + __logf(1.0f + __expf(lo0 - h0));

            a0 = na0; a1 = na1;
            if ((f & 31) == 31) sfb[wbuf][f >> 5] = a1;

            // roll emission queues; prefetch t+3 (clamped; off the chain)
            e0q0 = e0q1; e0q1 = e0q2;
            e1q0 = e1q1; e1q1 = e1q2;
            int tpf = t + 3; if (tpf > Tn - 1) tpf = Tn - 1;
            e0q2 = __ldg(xin + (size_t)tpf * Nn + tg0);
            e1q2 = __ldg(xin + (size_t)tpf * Nn + tg1);
            NBAR(2, 128);
        }

        if (l0 == tssel - 1) s_res[1] = a0;
        if (l1 == tssel - 1) s_res[1] = a1;
    }

    // ---- in-CTA combine: all 192 threads arrive exactly once ----
    __syncthreads();
    if (tid == 0) out[b] = s_res[0] - s_res[1];
}

// ---------------------------------------------------------------------------
extern "C" void kernel_launch(void* const* d_in, const int* in_sizes, int n_in,
                              void* d_out, int out_size) {
    const float* in    = (const float*)d_in[0];   // input  [B,T,N] f32
    const int*   tgt   = (const int*)  d_in[1];   // target [B,L]   i32
    const int*   tsz   = (const int*)  d_in[2];   // target_size [B]
    const float* trans = (const float*)d_in[3];   // trans  [N,N]   f32
    float* out = (float*)d_out;
    (void)in_sizes; (void)n_in; (void)out_size;

    asg_main<<<Bn, 192>>>(in, tgt, tsz, trans, out);
}

// round 12
// speedup vs baseline: 1.1111x; 1.1111x over previous
#include <cuda_runtime.h>
#include <cstdint>
#include <cstddef>

#define NEGV (-1e30f)

static const int Bn = 128;
static const int Tn = 2048;
static const int Nn = 64;
static const int Ln = 256;

// result scratch + combine flags (device globals: allocation-free)
__device__ float g_fcc[Bn];
__device__ float g_fac[Bn];
__device__ unsigned g_flag[Bn];   // monotonic; parity selects per-call 2nd arriver

// ---------------------------------------------------------------------------
// Packed f32x2 helpers (Blackwell: fma.rn.f32x2 only reachable via PTX)
// ---------------------------------------------------------------------------
__device__ __forceinline__ void fma2(unsigned long long& acc,
                                     unsigned long long e,
                                     unsigned long long w) {
    asm("fma.rn.f32x2 %0, %1, %2, %0;" : "+l"(acc) : "l"(e), "l"(w));
}
__device__ __forceinline__ unsigned long long add2(unsigned long long a,
                                                   unsigned long long b) {
    unsigned long long r;
    asm("add.rn.f32x2 %0, %1, %2;" : "=l"(r) : "l"(a), "l"(b));
    return r;
}
__device__ __forceinline__ float lo_plus_hi(unsigned long long v) {
    float lo, hi;
    asm("mov.b64 {%0, %1}, %2;" : "=f"(lo), "=f"(hi) : "l"(v));
    return lo + hi;
}
__device__ __forceinline__ unsigned long long packexp2(const float* p) {
    float a = __expf(p[0]), b = __expf(p[1]);
    unsigned long long r;
    asm("mov.b64 %0, {%1, %2};" : "=l"(r) : "f"(a), "f"(b));
    return r;
}
__device__ __forceinline__ void cp4(void* dst, const void* src) {
    unsigned int d = (unsigned int)__cvta_generic_to_shared(dst);
    asm volatile("cp.async.ca.shared.global [%0], [%1], 4;" :: "r"(d), "l"(src) : "memory");
}
#define CP_COMMIT() asm volatile("cp.async.commit_group;" ::: "memory")
#define CP_WAIT5()  asm volatile("cp.async.wait_group 5;" ::: "memory")

// ---------------------------------------------------------------------------
// Single kernel, grid 256 x 128 threads.
//
// blocks 0..127: fcc for batch b — PHASE-SPLIT over 4 warps:
//   Phase 1 (all warps): warp w owns m in [16w,16w+16); lane computes partial
//     dot products for classes n0=2*lane, n1=2*lane+1 (16 FFMA2, 4 broadcast
//     LDS.128), stores packed partial via STS.64. Mid-step __syncthreads.
//   Phase 2: warps 0-1 (thread = class n) sum the 4 partials, apply EXACT
//     power-of-2 renorm (integer exponent strip of E_prev[0]), store E';
//     warps 2-3 run the cp.async x_t staging ring at prefetch distance 7
//     (slot t+1 is wait-completed at step t-1 and published by that step's
//     closing barrier — loaders and readers are different warps).
//   End-of-step __syncthreads.
//
// blocks 128..255: fac for batch b — 4 homogeneous warps, thread = 2 target
//   lanes; emissions x[t][tg] prefetched into per-thread register queues.
//
// The (fcc b, fac b) pair's 2nd finisher writes out[b] (parity atomic).
// ---------------------------------------------------------------------------
__global__ void __launch_bounds__(128, 1) asg_main(
    const float* __restrict__ xin_all, const int* __restrict__ tgt_all,
    const int* __restrict__ tsz_all, const float* __restrict__ trans,
    float* __restrict__ out)
{
    __shared__ __align__(16) float sx[8][64];     // fcc x_t staging ring
    __shared__ __align__(16) float sE[2][64];     // fcc state, double buffered
    __shared__ __align__(16) float part[4][64];   // fcc per-warp partials
    __shared__ float sfb[2][4];                   // fac warp-boundary, dbl buf

    const int role = blockIdx.x >> 7;             // 0: fcc, 1: fac
    const int b = blockIdx.x & 127;
    const int tid = threadIdx.x;
    const float* xin = xin_all + (size_t)b * Tn * Nn;

    if (role == 0) {
        // ================= fcc: scaled-exp forward scan (phase-split) ======
        const int wid = tid >> 5;
        const int lane = tid & 31;
        const int m_base = 16 * wid;              // this warp's m-range
        const int n0 = 2 * lane, n1 = n0 + 1;     // this lane's classes

        // weights: exp(trans[n][m_base + j]) packed in m-pairs
        unsigned long long w2a[8], w2b[8];
        {
            const float* wr0 = trans + n0 * Nn + m_base;
            const float* wr1 = trans + n1 * Nn + m_base;
#pragma unroll
            for (int j = 0; j < 8; j++) {
                w2a[j] = packexp2(wr0 + 2 * j);
                w2b[j] = packexp2(wr1 + 2 * j);
            }
        }
        if (tid < 64) sE[0][tid] = __expf(xin[tid]);  // alpha0 = x0
        int iexp = 0;                             // sum of stripped exponents

        // prologue: warps 2-3 stage x_t for t = 1..7 (distance-7 ring)
        if (tid >= 64) {
            const int f = tid - 64;
#pragma unroll
            for (int tt = 1; tt <= 7; tt++) {
                cp4(&sx[tt & 7][f], xin + (size_t)tt * Nn + f);
                CP_COMMIT();
            }
            CP_WAIT5();                           // completes slots 1,2
        }
        __syncthreads();

        float p_cur = (tid < 64) ? __expf(sx[1][tid]) : 0.f;  // exp(x[1])

        for (int t = 1; t < Tn; ++t) {
            const int rbuf = (t + 1) & 1;         // E read buffer
            const int wbuf = t & 1;               // E write buffer

            // ---- phase 1: partial dot products over this warp's m-range ----
            const ulonglong2* eq =
                reinterpret_cast<const ulonglong2*>(&sE[rbuf][m_base]);
            ulonglong2 eA = eq[0], eB = eq[1], eC = eq[2], eD = eq[3];

            unsigned long long a0 = 0ull, a1 = 0ull;   // class n0
            unsigned long long b0 = 0ull, b1 = 0ull;   // class n1
            fma2(a0, eA.x, w2a[0]); fma2(b0, eA.x, w2b[0]);
            fma2(a1, eA.y, w2a[1]); fma2(b1, eA.y, w2b[1]);
            fma2(a0, eB.x, w2a[2]); fma2(b0, eB.x, w2b[2]);
            fma2(a1, eB.y, w2a[3]); fma2(b1, eB.y, w2b[3]);
            fma2(a0, eC.x, w2a[4]); fma2(b0, eC.x, w2b[4]);
            fma2(a1, eC.y, w2a[5]); fma2(b1, eC.y, w2b[5]);
            fma2(a0, eD.x, w2a[6]); fma2(b0, eD.x, w2b[6]);
            fma2(a1, eD.y, w2a[7]); fma2(b1, eD.y, w2b[7]);

            float S0 = lo_plus_hi(add2(a0, a1));
            float S1 = lo_plus_hi(add2(b0, b1));
            *reinterpret_cast<float2*>(&part[wid][n0]) = make_float2(S0, S1);
            __syncthreads();

            // ---- phase 2: combine partials / staging (warp-uniform split) --
            if (tid < 64) {
                const int n = tid;
                float s = (part[0][n] + part[1][n]) + (part[2][n] + part[3][n]);
                float e0 = sE[rbuf][0];
                int k = ((__float_as_int(e0) >> 23) & 0xff) - 127;
                iexp += k;
                float En = s * p_cur;             // p_cur = exp(x_t[n])
                En = __int_as_float(__float_as_int(En) - (k << 23)); // * 2^-k
                sE[wbuf][n] = En;
                // slot t+1: completed by WAIT5 at step t-1 (prologue for t=1),
                // published by that step's closing barrier.
                if (t + 1 < Tn) p_cur = __expf(sx[(t + 1) & 7][n]);
            } else {
                const int f = tid - 64;
                int tpf = t + 7; if (tpf > Tn - 1) tpf = Tn - 1;
                cp4(&sx[(t + 7) & 7][f], xin + (size_t)tpf * Nn + f);
                CP_COMMIT();
                CP_WAIT5();
            }
            __syncthreads();
        }

        // epilogue: fcc = iexp*ln2 + ln(sum_n E[n]); last buffer = 2047&1 = 1
        if (tid < 32) {
            float v = sE[1][tid] + sE[1][tid + 32];
#pragma unroll
            for (int o = 16; o > 0; o >>= 1)
                v += __shfl_xor_sync(0xffffffffu, v, o);
            if (tid == 0) {
                float fcc = (float)iexp * 0.69314718055994531f + __logf(v);
                g_fcc[b] = fcc;
                __threadfence();
                unsigned old = atomicAdd(&g_flag[b], 1u);
                if (old & 1u) {                   // 2nd arriver this call
                    __threadfence();
                    out[b] = fcc - g_fac[b];
                }
            }
        }
    } else {
        // ================= fac: log-domain constrained scan ================
        const int f = tid;                        // 0..127, lanes 2f, 2f+1
        const int l0 = 2 * f, l1 = 2 * f + 1;
        const int tg0 = tgt_all[b * Ln + l0];
        const int tg1 = tgt_all[b * Ln + l1];
        const int tgm = (l0 > 0) ? tgt_all[b * Ln + l0 - 1] : 0;
        const float ts0 = trans[tg0 * Nn + tg0];
        const float ts1 = trans[tg1 * Nn + tg1];
        const float tm0 = trans[tg0 * Nn + tgm];  // move into l0 (unused if l0==0)
        const float tm1 = trans[tg1 * Nn + tg0];  // move into l1
        const int tssel = tsz_all[b];

        float a0 = (l0 == 0) ? xin[tg0] : NEGV;   // alpha0[0] = x0[target[0]]
        float a1 = NEGV;
        if ((f & 31) == 31) sfb[0][f >> 5] = a1;

        // emission register queues (fixed per-thread addresses): t, t+1, t+2
        float e0q0 = __ldg(xin + 1 * (size_t)Nn + tg0);
        float e1q0 = __ldg(xin + 1 * (size_t)Nn + tg1);
        float e0q1 = __ldg(xin + 2 * (size_t)Nn + tg0);
        float e1q1 = __ldg(xin + 2 * (size_t)Nn + tg1);
        float e0q2 = __ldg(xin + 3 * (size_t)Nn + tg0);
        float e1q2 = __ldg(xin + 3 * (size_t)Nn + tg1);
        __syncthreads();

        for (int t = 1; t < Tn; ++t) {
            const int rb = (t + 1) & 1;
            const int wbuf = t & 1;

            float ap = __shfl_up_sync(0xffffffffu, a1, 1);
            float e0 = e0q0, e1 = e1q0;
            if ((f & 31) == 0) ap = (f == 0) ? NEGV : sfb[rb][(f >> 5) - 1];

            float st1 = a1 + ts1, mv1 = a0 + tm1; // uses OLD a0
            float h1 = fmaxf(st1, mv1), lo1 = fminf(st1, mv1);
            float na1 = e1 + h1 + __logf(1.0f + __expf(lo1 - h1));

            float st0 = a0 + ts0, mv0 = ap + tm0;
            float h0 = fmaxf(st0, mv0), lo0 = fminf(st0, mv0);
            float na0 = e0 + h0 + __logf(1.0f + __expf(lo0 - h0));

            a0 = na0; a1 = na1;
            if ((f & 31) == 31) sfb[wbuf][f >> 5] = a1;

            // roll emission queues; prefetch t+3 (clamped; off the chain)
            e0q0 = e0q1; e0q1 = e0q2;
            e1q0 = e1q1; e1q1 = e1q2;
            int tpf = t + 3; if (tpf > Tn - 1) tpf = Tn - 1;
            e0q2 = __ldg(xin + (size_t)tpf * Nn + tg0);
            e1q2 = __ldg(xin + (size_t)tpf * Nn + tg1);
            __syncthreads();
        }

        if (l0 == tssel - 1) g_fac[b] = a0;
        if (l1 == tssel - 1) g_fac[b] = a1;
        __syncthreads();
        if (tid == 0) {
            __threadfence();
            unsigned old = atomicAdd(&g_flag[b], 1u);
            if (old & 1u) {                       // 2nd arriver this call
                __threadfence();
                out[b] = g_fcc[b] - g_fac[b];
            }
        }
    }
}

// ---------------------------------------------------------------------------
extern "C" void kernel_launch(void* const* d_in, const int* in_sizes, int n_in,
                              void* d_out, int out_size) {
    const float* in    = (const float*)d_in[0];   // input  [B,T,N] f32
    const int*   tgt   = (const int*)  d_in[1];   // target [B,L]   i32
    const int*   tsz   = (const int*)  d_in[2];   // target_size [B]
    const float* trans = (const float*)d_in[3];   // trans  [N,N]   f32
    float* out = (float*)d_out;
    (void)in_sizes; (void)n_in; (void)out_size;

    asg_main<<<2 * Bn, 128>>>(in, tgt, tsz, trans, out);
}